// round 6
// baseline (speedup 1.0000x reference)
#include <cuda_runtime.h>
#include <cstdint>
#include <math.h>

#define NN      100000
#define IN_DIM  512
#define OUT_DIM 128

// ---------------------------------------------------------------------------
// Scratch. g_zero is cleared by one memset each call:
//   [0, 2*NN) int deg | 1024 float wf | 256 float cpre | 2 int barriers
// ---------------------------------------------------------------------------
#define OFF_WF   (2 * NN)
#define OFF_CPRE (2 * NN + 1024)
#define OFF_BAR  (2 * NN + 1024 + 256)
#define ZERO_INTS (2 * NN + 1024 + 256 + 2)
__device__ int   g_zero[ZERO_INTS];
__device__ float g_v   [2 * OUT_DIM];    // v1 = Wb@c1, v2 = Wb@c2
__device__ float g_u   [2 * IN_DIM];     // u_a = W2@v1, u_b = W1@v2
__device__ float g_k   [2];              // k1 = b2.v1+bb, k2 = b1.v2+bb
__device__ float g_p   [4 * NN];         // pfa, pfb, psa, psb

// ---------------------------------------------------------------------------
// Histogram over both src lists (blockIdx.y selects list).
// ---------------------------------------------------------------------------
__global__ void hist_both(const int* __restrict__ srcA, int neA,
                          const int* __restrict__ srcB, int neB,
                          int* __restrict__ deg)
{
    const int* src = blockIdx.y ? srcB : srcA;
    int ne = blockIdx.y ? neB : neA;
    int* dg = deg + blockIdx.y * NN;
    int e0 = (blockIdx.x * blockDim.x + threadIdx.x) * 4;
    if (e0 + 3 < ne) {
        int4 s = *(const int4*)(src + e0);
        atomicAdd(&dg[s.x], 1);
        atomicAdd(&dg[s.y], 1);
        atomicAdd(&dg[s.z], 1);
        atomicAdd(&dg[s.w], 1);
    } else {
        for (int e = e0; e < ne; e++) atomicAdd(&dg[src[e]], 1);
    }
}

// ---------------------------------------------------------------------------
// wf[c] = sum_v deg1[v]*feat[v,c] ; wf[512+c] = sum_v deg2[v]*feat[v,c]
// ---------------------------------------------------------------------------
__global__ __launch_bounds__(256) void wf_kernel(
    const float* __restrict__ feat, const int* __restrict__ deg1,
    const int* __restrict__ deg2, float* __restrict__ wf, int n)
{
    __shared__ float red[256 * 8];
    int t = threadIdx.x;
    int half = t >> 7, c = t & 127;
    const float4* f4 = (const float4*)feat;

    float4 a1 = make_float4(0.f, 0.f, 0.f, 0.f);
    float4 a2 = make_float4(0.f, 0.f, 0.f, 0.f);
    for (int v = blockIdx.x * 2 + half; v < n; v += gridDim.x * 2) {
        float w1 = (float)__ldg(&deg1[v]);
        float w2 = (float)__ldg(&deg2[v]);
        float4 x = __ldg(&f4[(size_t)v * 128 + c]);
        a1.x += w1 * x.x; a1.y += w1 * x.y; a1.z += w1 * x.z; a1.w += w1 * x.w;
        a2.x += w2 * x.x; a2.y += w2 * x.y; a2.z += w2 * x.z; a2.w += w2 * x.w;
    }
    *(float4*)&red[t * 8]     = a1;
    *(float4*)&red[t * 8 + 4] = a2;
    __syncthreads();
    if (half == 0) {
        int p = (t + 128) * 8;
        a1.x += red[p];     a1.y += red[p + 1]; a1.z += red[p + 2]; a1.w += red[p + 3];
        a2.x += red[p + 4]; a2.y += red[p + 5]; a2.z += red[p + 6]; a2.w += red[p + 7];
        atomicAdd(&wf[c * 4],     a1.x);
        atomicAdd(&wf[c * 4 + 1], a1.y);
        atomicAdd(&wf[c * 4 + 2], a1.z);
        atomicAdd(&wf[c * 4 + 3], a1.w);
        atomicAdd(&wf[IN_DIM + c * 4],     a2.x);
        atomicAdd(&wf[IN_DIM + c * 4 + 1], a2.y);
        atomicAdd(&wf[IN_DIM + c * 4 + 2], a2.z);
        atomicAdd(&wf[IN_DIM + c * 4 + 3], a2.w);
    }
}

// ---------------------------------------------------------------------------
// Fused small chain: cpre -> (grid barrier) -> v -> (grid barrier) -> u, kc.
// 128 blocks x 128 threads (always co-resident on 148 SMs). Barrier counters
// live in the memset-zeroed region. Cross-block reads use __ldcg (L2).
// ---------------------------------------------------------------------------
__device__ __forceinline__ void grid_bar(int* cnt, int nblocks) {
    __threadfence();
    __syncthreads();
    if (threadIdx.x == 0) {
        atomicAdd(cnt, 1);
        while (*(volatile int*)cnt < nblocks) {}
    }
    __syncthreads();
}

__global__ __launch_bounds__(128) void chain_kernel(
    const float* __restrict__ W1, const float* __restrict__ W2,
    const float* __restrict__ Wb, const float* __restrict__ b1,
    const float* __restrict__ b2, const float* __restrict__ bb,
    const float* __restrict__ wf, float* __restrict__ cpre,
    float* __restrict__ v, float* __restrict__ u, float* __restrict__ kc,
    int* __restrict__ bar, float inv_n)
{
    int b = blockIdx.x;          // 0..127
    int t = threadIdx.x;         // 0..127
    int warp = t >> 5, lane = t & 31;

    // phase 1: cpre[h*128+t] partials (block = one 8-k chunk of one half)
    {
        int hh = b >> 6, chunk = b & 63;
        const float* W = hh ? W2 : W1;
        const float* w = wf + hh * IN_DIM + chunk * 8;
        const float* Wc = W + (size_t)(chunk * 8) * OUT_DIM + t;
        float s = 0.f;
        #pragma unroll
        for (int k = 0; k < 8; k++)
            s += __ldg(&w[k]) * __ldg(&Wc[k * OUT_DIM]);
        atomicAdd(&cpre[hh * OUT_DIM + t], s);
    }
    grid_bar(&bar[0], 128);

    // phase 2: v (warp per output; blocks 0..63 cover 256 outputs)
    if (b < 64) {
        int gw = b * 4 + warp;
        int half = gw >> 7, d = gw & 127;
        const float* bh = half ? b2 : b1;
        const float* cp = cpre + half * OUT_DIM;
        const float* wr = Wb + (size_t)d * OUT_DIM;
        float s = 0.f;
        #pragma unroll
        for (int j = 0; j < 4; j++) {
            int e = lane + 32 * j;
            float c = 1.0f / (1.0f + expf(-(__ldcg(&cp[e]) * inv_n + __ldg(&bh[e]))));
            s += __ldg(&wr[e]) * c;
        }
        #pragma unroll
        for (int o = 16; o; o >>= 1) s += __shfl_xor_sync(0xffffffffu, s, o);
        if (lane == 0) v[half * OUT_DIM + d] = s;
    }
    grid_bar(&bar[1], 128);

    // phase 3: u (512 warps x 2 outputs = 1024) + kc
    int W512 = b * 4 + warp;     // 0..511
    #pragma unroll
    for (int rep = 0; rep < 2; rep++) {
        int idx = W512 + rep * 512;          // 0..1023
        int half = idx >> 9;                 // 0: u_a (W2,v1)  1: u_b (W1,v2)
        int tt = idx & 511;
        const float* W = half ? W1 : W2;
        const float* vv = v + half * OUT_DIM;
        const float* wr = W + (size_t)tt * OUT_DIM;
        float s = 0.f;
        #pragma unroll
        for (int j = 0; j < 4; j++) {
            int d = lane + 32 * j;
            s += __ldg(&wr[d]) * __ldcg(&vv[d]);
        }
        #pragma unroll
        for (int o = 16; o; o >>= 1) s += __shfl_xor_sync(0xffffffffu, s, o);
        if (lane == 0) u[half * IN_DIM + tt] = s;
    }
    if (W512 < 2) {                          // kc[0]=b2.v1+bb, kc[1]=b1.v2+bb
        const float* bv = W512 ? b1 : b2;
        const float* vv = v + W512 * OUT_DIM;
        float s = 0.f;
        #pragma unroll
        for (int j = 0; j < 4; j++) {
            int d = lane + 32 * j;
            s += __ldg(&bv[d]) * __ldcg(&vv[d]);
        }
        #pragma unroll
        for (int o = 16; o; o >>= 1) s += __shfl_xor_sync(0xffffffffu, s, o);
        if (lane == 0) kc[W512] = s + __ldg(bb);
    }
}

// ---------------------------------------------------------------------------
// p body: warp-per-node dot with u_a and u_b (su preloaded in smem).
// ---------------------------------------------------------------------------
__device__ __forceinline__ void p_block(
    const float* __restrict__ X, const float* __restrict__ u,
    float* __restrict__ pa, float* __restrict__ pb, int node_base, int n)
{
    __shared__ __align__(16) float su[2 * IN_DIM];
    for (int i = threadIdx.x; i < 2 * IN_DIM; i += 256) su[i] = u[i];
    __syncthreads();
    int warp = threadIdx.x >> 5, lane = threadIdx.x & 31;
    int v = node_base + warp;
    if (v >= n) return;
    const float4* x4 = (const float4*)(X + (size_t)v * IN_DIM);
    const float4* ua4 = (const float4*)su;
    const float4* ub4 = (const float4*)(su + IN_DIM);
    float sa = 0.f, sb = 0.f;
    #pragma unroll
    for (int j = 0; j < 4; j++) {
        float4 x = x4[lane + 32 * j];
        float4 a = ua4[lane + 32 * j];
        float4 b = ub4[lane + 32 * j];
        sa += x.x * a.x + x.y * a.y + x.z * a.z + x.w * a.w;
        sb += x.x * b.x + x.y * b.y + x.z * b.z + x.w * b.w;
    }
    #pragma unroll
    for (int o = 16; o; o >>= 1) {
        sa += __shfl_xor_sync(0xffffffffu, sa, o);
        sb += __shfl_xor_sync(0xffffffffu, sb, o);
    }
    if (lane == 0) { pa[v] = sa; pb[v] = sb; }
}

// ---------------------------------------------------------------------------
// Scatter body: one atomic per edge, o[dst] += p[src].
// ---------------------------------------------------------------------------
__device__ __forceinline__ void scatter_block(
    const int* __restrict__ src, const int* __restrict__ dst,
    const float* __restrict__ p, float* __restrict__ o, int bx, int ne)
{
    int e0 = (bx * 256 + threadIdx.x) * 4;
    if (e0 + 3 < ne) {
        int4 s = *(const int4*)(src + e0);
        int4 d = *(const int4*)(dst + e0);
        atomicAdd(&o[d.x], __ldg(&p[s.x]));
        atomicAdd(&o[d.y], __ldg(&p[s.y]));
        atomicAdd(&o[d.z], __ldg(&p[s.z]));
        atomicAdd(&o[d.w], __ldg(&p[s.w]));
    } else {
        for (int e = e0; e < ne; e++) atomicAdd(&o[dst[e]], __ldg(&p[src[e]]));
    }
}

// ---------------------------------------------------------------------------
// Stage A: p_feat (blocks [0,G_PF)) || init_out (blocks [G_PF, G_PF+G_INIT))
// ---------------------------------------------------------------------------
__global__ __launch_bounds__(256) void pfeat_init_kernel(
    const float* __restrict__ feat, const float* __restrict__ u,
    const float* __restrict__ kc, float* __restrict__ pp,
    float* __restrict__ out, int n, int G_PF)
{
    if ((int)blockIdx.x < G_PF) {
        p_block(feat, u, pp, pp + NN, blockIdx.x * 8, n);
    } else {
        int i = ((int)blockIdx.x - G_PF) * 256 + threadIdx.x;
        if (i < n) {
            float k1 = __ldg(&kc[0]), k2 = __ldg(&kc[1]);
            out[i]         = k1;   // sc1 = h2.v1
            out[n + i]     = k2;   // sc2 = h1.v2
            out[2 * n + i] = k1;   // sc3 = h4.v1
            out[3 * n + i] = k2;   // sc4 = h3.v2
        }
    }
}

// ---------------------------------------------------------------------------
// Stage B: scatter_feat (L2-atomic bound) || p_shuf (DRAM bound), one grid.
//   blocks [0,gx2):        edges2 -> out[0:n]   += pfa[src]
//   blocks [gx2,gx2+gx1):  edges1 -> out[n:2n]  += pfb[src]
//   blocks [gx2+gx1, ...): p_shuf -> psa, psb
// ---------------------------------------------------------------------------
__global__ __launch_bounds__(256) void scatterfeat_pshuf_kernel(
    const float* __restrict__ shuf, const float* __restrict__ u,
    float* __restrict__ pp, float* __restrict__ out,
    const int* __restrict__ src2, const int* __restrict__ dst2, int ne2,
    const int* __restrict__ src1, const int* __restrict__ dst1, int ne1,
    int n, int gx2, int gx1)
{
    int b = blockIdx.x;
    if (b < gx2) {
        scatter_block(src2, dst2, pp, out, b, ne2);
    } else if (b < gx2 + gx1) {
        scatter_block(src1, dst1, pp + NN, out + n, b - gx2, ne1);
    } else {
        p_block(shuf, u, pp + 2 * NN, pp + 3 * NN, (b - gx2 - gx1) * 8, n);
    }
}

// ---------------------------------------------------------------------------
// Stage C: scatter_shuf (both lists, one grid).
// ---------------------------------------------------------------------------
__global__ __launch_bounds__(256) void scattershuf_kernel(
    const float* __restrict__ pp, float* __restrict__ out,
    const int* __restrict__ src2, const int* __restrict__ dst2, int ne2,
    const int* __restrict__ src1, const int* __restrict__ dst1, int ne1,
    int n, int gx2)
{
    int b = blockIdx.x;
    if (b < gx2) scatter_block(src2, dst2, pp + 2 * NN, out + 2 * n, b, ne2);
    else         scatter_block(src1, dst1, pp + 3 * NN, out + 3 * n, b - gx2, ne1);
}

// ---------------------------------------------------------------------------
// Launch
// ---------------------------------------------------------------------------
extern "C" void kernel_launch(void* const* d_in, const int* in_sizes, int n_in,
                              void* d_out, int out_size)
{
    const float* feat = (const float*)d_in[0];
    const float* shuf = (const float*)d_in[1];
    const int*   src1 = (const int*)d_in[2];
    const int*   dst1 = (const int*)d_in[3];
    const int*   src2 = (const int*)d_in[4];
    const int*   dst2 = (const int*)d_in[5];
    const float* W1   = (const float*)d_in[6];
    const float* b1   = (const float*)d_in[7];
    const float* W2   = (const float*)d_in[8];
    const float* b2   = (const float*)d_in[9];
    const float* Wb   = (const float*)d_in[10];
    const float* bb   = (const float*)d_in[11];
    float* out = (float*)d_out;

    const int n   = in_sizes[0] / IN_DIM;   // 100000
    const int ne1 = in_sizes[2];
    const int ne2 = in_sizes[4];

    void* p;
    cudaGetSymbolAddress(&p, g_zero);
    int*   deg  = (int*)p;
    float* wf   = (float*)((int*)p + OFF_WF);
    float* cpre = (float*)((int*)p + OFF_CPRE);
    int*   bar  = (int*)p + OFF_BAR;
    cudaGetSymbolAddress(&p, g_v);  float* v  = (float*)p;
    cudaGetSymbolAddress(&p, g_u);  float* u  = (float*)p;
    cudaGetSymbolAddress(&p, g_k);  float* kc = (float*)p;
    cudaGetSymbolAddress(&p, g_p);  float* pp = (float*)p;

    // 0) zero deg+wf+cpre+barriers with one memset
    cudaMemsetAsync(deg, 0, ZERO_INTS * sizeof(int));

    // 1) out-degree histograms (both lists, one launch)
    int gx1 = (ne1 / 4 + 255) / 256, gx2 = (ne2 / 4 + 255) / 256;
    {
        dim3 grid(gx1 > gx2 ? gx1 : gx2, 2);
        hist_both<<<grid, 256>>>(src1, ne1, src2, ne2, deg);
    }

    // 2) weighted row-sums of feat
    wf_kernel<<<1024, 256>>>(feat, deg, deg + NN, wf, n);

    // 3) fused tiny chain: cpre -> v -> u, kc (one launch, grid barriers)
    chain_kernel<<<128, 128>>>(W1, W2, Wb, b1, b2, bb, wf, cpre, v, u, kc,
                               bar, 1.0f / (float)n);

    // 4) p_feat || init_out
    int G_PF = (n + 7) / 8;                // 12500
    int G_INIT = (n + 255) / 256;          // 391
    pfeat_init_kernel<<<G_PF + G_INIT, 256>>>(feat, u, kc, pp, out, n, G_PF);

    // 5) scatter_feat || p_shuf (heterogeneous overlap in one grid)
    scatterfeat_pshuf_kernel<<<gx2 + gx1 + G_PF, 256>>>(
        shuf, u, pp, out, src2, dst2, ne2, src1, dst1, ne1, n, gx2, gx1);

    // 6) scatter_shuf
    scattershuf_kernel<<<gx2 + gx1, 256>>>(
        pp, out, src2, dst2, ne2, src1, dst1, ne1, n, gx2);
}